// round 4
// baseline (speedup 1.0000x reference)
#include <cuda_runtime.h>
#include <cuda_bf16.h>

// Problem constants
#define ZB 8
#define ZC 128
#define ZW 64
#define ZH 64
#define LDIM 16
#define KCODES 256
#define CDIM 8
#define NPOS (ZB * ZW * ZH)   // 32768 spatial positions
#define WHPLANE (ZW * ZH)     // 4096

typedef unsigned long long u64;

// log2(e)^2 and -2*log2(e)^2 ; 1/S2n to un-scale the soft accumulator
#define S1 2.0813689810056077f
#define S2n (-4.1627379620112154f)
#define INV_S2n (-0.24022650695910071f)

// ---- packed f32x2 helpers (sm_103a) ----
__device__ __forceinline__ u64 pk2(float lo, float hi) {
    u64 r; asm("mov.b64 %0, {%1, %2};" : "=l"(r) : "f"(lo), "f"(hi)); return r;
}
__device__ __forceinline__ void upk2(u64 p, float& lo, float& hi) {
    asm("mov.b64 {%0, %1}, %2;" : "=f"(lo), "=f"(hi) : "l"(p));
}
__device__ __forceinline__ u64 ffma2(u64 a, u64 b, u64 c) {
    u64 d; asm("fma.rn.f32x2 %0, %1, %2, %3;" : "=l"(d) : "l"(a), "l"(b), "l"(c)); return d;
}
__device__ __forceinline__ u64 fadd2(u64 a, u64 b) {
    u64 d; asm("add.rn.f32x2 %0, %1, %2;" : "=l"(d) : "l"(a), "l"(b)); return d;
}
__device__ __forceinline__ float sqrt_ap(float x) {
    float r; asm("sqrt.approx.f32 %0, %1;" : "=f"(r) : "f"(x)); return r;
}
__device__ __forceinline__ float ex2_ap(float x) {
    float r; asm("ex2.approx.f32 %0, %1;" : "=f"(r) : "f"(x)); return r;
}

// One block = one latent l (blockIdx.y) x 256 positions (blockIdx.x), 128 threads.
// Each thread owns TWO positions; f32x2 lanes = (pos0, pos1) for the SAME code.
// Codes live lane-duplicated in smem so LDS.128 feeds fma.rn.f32x2 directly.
// No horizontal reductions anywhere; accumulators are per-lane = per-position.
__global__ void __launch_bounds__(128)
sth_kernel(const float* __restrict__ z, const float* __restrict__ codes,
           float* __restrict__ out_soft, float* __restrict__ out_hard,
           float* __restrict__ out_idx)
{
    const int l    = blockIdx.y;
    const int tid  = threadIdx.x;
    const int pos0 = blockIdx.x * 256 + tid;
    const int pos1 = pos0 + 128;

    __shared__ u64 sct[KCODES][CDIM];  // (S2n*c_k[i], S2n*c_k[i])  16 KB
    __shared__ u64 ssn[KCODES];        // (S1*||c_k||^2, same)       2 KB

    // Cooperative codebook load: thread t handles codes t and t+128
    #pragma unroll
    for (int r = 0; r < 2; r++) {
        const int k = tid + r * 128;
        const float4* cl = reinterpret_cast<const float4*>(codes)
                         + (size_t)l * (KCODES * 2) + 2 * k;
        const float4 a = cl[0];
        const float4 b = cl[1];
        u64* row = sct[k];
        row[0] = pk2(S2n * a.x, S2n * a.x);
        row[1] = pk2(S2n * a.y, S2n * a.y);
        row[2] = pk2(S2n * a.z, S2n * a.z);
        row[3] = pk2(S2n * a.w, S2n * a.w);
        row[4] = pk2(S2n * b.x, S2n * b.x);
        row[5] = pk2(S2n * b.y, S2n * b.y);
        row[6] = pk2(S2n * b.z, S2n * b.z);
        row[7] = pk2(S2n * b.w, S2n * b.w);
        const float cn = S1 * (a.x * a.x + a.y * a.y + a.z * a.z + a.w * a.w
                             + b.x * b.x + b.y * b.y + b.z * b.z + b.w * b.w);
        ssn[k] = pk2(cn, cn);
    }
    __syncthreads();

    // Load both positions' latent vectors (NCHW -> channel stride 4096)
    const int bb0 = pos0 >> 12, wh0 = pos0 & 4095;
    const int bb1 = pos1 >> 12, wh1 = pos1 & 4095;
    const float* zp0 = z + ((size_t)bb0 * ZC + (size_t)l * CDIM) * WHPLANE + wh0;
    const float* zp1 = z + ((size_t)bb1 * ZC + (size_t)l * CDIM) * WHPLANE + wh1;

    u64 hd[CDIM];
    float hn0 = 0.f, hn1 = 0.f;
    #pragma unroll
    for (int i = 0; i < CDIM; i++) {
        const float a = zp0[i * WHPLANE];
        const float b = zp1[i * WHPLANE];
        hn0 = fmaf(a, a, hn0);
        hn1 = fmaf(b, b, hn1);
        hd[i] = pk2(a, b);
    }
    const u64 hn2p = pk2(S1 * hn0, S1 * hn1);

    // Per-lane (= per-position) accumulators
    u64 acc[CDIM];
    #pragma unroll
    for (int i = 0; i < CDIM; i++) acc[i] = 0ull;
    u64 sume2 = 0ull;
    float mind0 = 3.4e38f, mind1 = 3.4e38f;
    int   mink0 = 0,        mink1 = 0;

    #pragma unroll 4
    for (int k = 0; k < KCODES; k++) {
        const ulonglong2 q01 = reinterpret_cast<const ulonglong2*>(sct[k])[0];
        const ulonglong2 q23 = reinterpret_cast<const ulonglong2*>(sct[k])[1];
        const ulonglong2 q45 = reinterpret_cast<const ulonglong2*>(sct[k])[2];
        const ulonglong2 q67 = reinterpret_cast<const ulonglong2*>(sct[k])[3];

        // d2' lanes = (pos0, pos1): seed with scn'+hn2', then 8 packed FMAs
        u64 dp = fadd2(ssn[k], hn2p);
        dp = ffma2(hd[0], q01.x, dp);
        dp = ffma2(hd[1], q01.y, dp);
        dp = ffma2(hd[2], q23.x, dp);
        dp = ffma2(hd[3], q23.y, dp);
        dp = ffma2(hd[4], q45.x, dp);
        dp = ffma2(hd[5], q45.y, dp);
        dp = ffma2(hd[6], q67.x, dp);
        dp = ffma2(hd[7], q67.y, dp);

        float d0, d1;
        upk2(dp, d0, d1);

        // argmin per position (exact compare; scale positive, strict '<')
        if (d0 < mind0) { mind0 = d0; mink0 = k; }
        if (d1 < mind1) { mind1 = d1; mink1 = k; }

        // e = exp(-dist) = 2^(-sqrt(S1*d2))
        const float e0 = ex2_ap(-sqrt_ap(fabsf(d0)));
        const float e1 = ex2_ap(-sqrt_ap(fabsf(d1)));
        const u64 ep = pk2(e0, e1);
        sume2 = fadd2(sume2, ep);

        acc[0] = ffma2(ep, q01.x, acc[0]);
        acc[1] = ffma2(ep, q01.y, acc[1]);
        acc[2] = ffma2(ep, q23.x, acc[2]);
        acc[3] = ffma2(ep, q23.y, acc[3]);
        acc[4] = ffma2(ep, q45.x, acc[4]);
        acc[5] = ffma2(ep, q45.y, acc[5]);
        acc[6] = ffma2(ep, q67.x, acc[6]);
        acc[7] = ffma2(ep, q67.y, acc[7]);
    }

    float se0, se1;
    upk2(sume2, se0, se1);
    const float inv0 = INV_S2n / se0;
    const float inv1 = INV_S2n / se1;

    float s0[CDIM], s1[CDIM];
    #pragma unroll
    for (int i = 0; i < CDIM; i++) {
        float a, b;
        upk2(acc[i], a, b);
        s0[i] = a * inv0;
        s1[i] = b * inv1;
    }

    // soft: (B,W,H,C), c = l*8 + cd -> offset pos*128 + l*8 (32B-aligned)
    {
        float4* sp0 = reinterpret_cast<float4*>(out_soft + (size_t)pos0 * ZC + (size_t)l * CDIM);
        sp0[0] = make_float4(s0[0], s0[1], s0[2], s0[3]);
        sp0[1] = make_float4(s0[4], s0[5], s0[6], s0[7]);
        float4* sp1 = reinterpret_cast<float4*>(out_soft + (size_t)pos1 * ZC + (size_t)l * CDIM);
        sp1[0] = make_float4(s1[0], s1[1], s1[2], s1[3]);
        sp1[1] = make_float4(s1[4], s1[5], s1[6], s1[7]);
    }

    if (out_hard) {
        // Re-read the winning codes from global (L2-hot, 32B each)
        const float4* cw0 = reinterpret_cast<const float4*>(codes)
                          + ((size_t)l * KCODES + mink0) * 2;
        const float4* cw1 = reinterpret_cast<const float4*>(codes)
                          + ((size_t)l * KCODES + mink1) * 2;
        float4* hp0 = reinterpret_cast<float4*>(out_hard + (size_t)pos0 * ZC + (size_t)l * CDIM);
        float4* hp1 = reinterpret_cast<float4*>(out_hard + (size_t)pos1 * ZC + (size_t)l * CDIM);
        hp0[0] = cw0[0];
        hp0[1] = cw0[1];
        hp1[0] = cw1[0];
        hp1[1] = cw1[1];
    }
    if (out_idx) {
        out_idx[(size_t)pos0 * LDIM + l] = (float)mink0;
        out_idx[(size_t)pos1 * LDIM + l] = (float)mink1;
    }
}

extern "C" void kernel_launch(void* const* d_in, const int* in_sizes, int n_in,
                              void* d_out, int out_size) {
    const float* z     = (const float*)d_in[0];
    const float* codes = (const float*)d_in[1];
    float* out = (float*)d_out;

    const long long softN = (long long)NPOS * ZC;   // 4,194,304
    const long long idxN  = (long long)NPOS * LDIM; // 524,288

    float* soft = out;
    float* hard = ((long long)out_size >= 2 * softN) ? out + softN : nullptr;
    float* idxo = ((long long)out_size >= 2 * softN + idxN) ? out + 2 * softN : nullptr;

    dim3 grid(NPOS / 256, LDIM);
    sth_kernel<<<grid, 128>>>(z, codes, soft, hard, idxo);
}

// round 5
// speedup vs baseline: 1.1140x; 1.1140x over previous
#include <cuda_runtime.h>
#include <cuda_bf16.h>

// Problem constants
#define ZB 8
#define ZC 128
#define ZW 64
#define ZH 64
#define LDIM 16
#define KCODES 256
#define CDIM 8
#define NPOS (ZB * ZW * ZH)   // 32768 spatial positions
#define WHPLANE (ZW * ZH)     // 4096

typedef unsigned long long u64;

// log2(e)^2 and -2*log2(e)^2 ; 1/S2n to un-scale the soft accumulator
#define S1 2.0813689810056077f
#define S2n (-4.1627379620112154f)
#define INV_S2n (-0.24022650695910071f)

// ---- packed f32x2 helpers (sm_103a) ----
__device__ __forceinline__ u64 pk2(float lo, float hi) {
    u64 r; asm("mov.b64 %0, {%1, %2};" : "=l"(r) : "f"(lo), "f"(hi)); return r;
}
__device__ __forceinline__ void upk2(u64 p, float& lo, float& hi) {
    asm("mov.b64 {%0, %1}, %2;" : "=f"(lo), "=f"(hi) : "l"(p));
}
__device__ __forceinline__ u64 ffma2(u64 a, u64 b, u64 c) {
    u64 d; asm("fma.rn.f32x2 %0, %1, %2, %3;" : "=l"(d) : "l"(a), "l"(b), "l"(c)); return d;
}
__device__ __forceinline__ u64 fadd2(u64 a, u64 b) {
    u64 d; asm("add.rn.f32x2 %0, %1, %2;" : "=l"(d) : "l"(a), "l"(b)); return d;
}
__device__ __forceinline__ float sqrt_ap(float x) {
    float r; asm("sqrt.approx.f32 %0, %1;" : "=f"(r) : "f"(x)); return r;
}
__device__ __forceinline__ float ex2_ap(float x) {
    float r; asm("ex2.approx.f32 %0, %1;" : "=f"(r) : "f"(x)); return r;
}

// One block = one latent l (blockIdx.y) x 256 positions (blockIdx.x).
// Each thread owns one (pos, l): loops over K=256 codes in PAIRS.
// f32x2 lanes = (code 2j, code 2j+1) of the same channel: the dot chain
// yields both d2 values with no horizontal reduction, and norms arrive as
// a pre-packed u64 so no per-iter packing MOVs remain.
__global__ void __launch_bounds__(256)
sth_kernel(const float* __restrict__ z, const float* __restrict__ codes,
           float* __restrict__ out_soft, float* __restrict__ out_hard,
           float* __restrict__ out_idx)
{
    const int l   = blockIdx.y;
    const int tid = threadIdx.x;
    const int pos = blockIdx.x * 256 + tid;

    // Transposed, pre-scaled codebook: sct[j][i] = (S2n*c_{2j}[i], S2n*c_{2j+1}[i])
    __shared__ u64 sct[KCODES / 2][CDIM];  // 8 KB
    __shared__ u64 ssn[KCODES / 2];        // (S1*||c_2j||^2, S1*||c_2j+1||^2) 1 KB

    // Cooperative codebook load: one code per thread (256 threads == 256 codes)
    {
        const float4* cl = reinterpret_cast<const float4*>(codes)
                         + (size_t)l * (KCODES * 2) + 2 * tid;
        const float4 a = cl[0];
        const float4 b = cl[1];
        float* sf = reinterpret_cast<float*>(sct);
        const int j = tid >> 1, lane = tid & 1;
        const int base = j * (CDIM * 2) + lane;
        sf[base +  0] = S2n * a.x;
        sf[base +  2] = S2n * a.y;
        sf[base +  4] = S2n * a.z;
        sf[base +  6] = S2n * a.w;
        sf[base +  8] = S2n * b.x;
        sf[base + 10] = S2n * b.y;
        sf[base + 12] = S2n * b.z;
        sf[base + 14] = S2n * b.w;
        reinterpret_cast<float*>(ssn)[tid] =
            S1 * (a.x * a.x + a.y * a.y + a.z * a.z + a.w * a.w
                + b.x * b.x + b.y * b.y + b.z * b.z + b.w * b.w);
    }
    __syncthreads();

    // Load this position's latent vector hv (8 channels, NCHW -> stride 4096)
    const int bb = pos >> 12;
    const int wh = pos & 4095;
    const float* zp = z + ((size_t)bb * ZC + (size_t)l * CDIM) * WHPLANE + wh;
    const float h0 = zp[0 * WHPLANE];
    const float h1 = zp[1 * WHPLANE];
    const float h2 = zp[2 * WHPLANE];
    const float h3 = zp[3 * WHPLANE];
    const float h4 = zp[4 * WHPLANE];
    const float h5 = zp[5 * WHPLANE];
    const float h6 = zp[6 * WHPLANE];
    const float h7 = zp[7 * WHPLANE];
    const float hn2 = S1 * (h0 * h0 + h1 * h1 + h2 * h2 + h3 * h3
                          + h4 * h4 + h5 * h5 + h6 * h6 + h7 * h7);

    // h duplicated into both lanes (once, outside the loop)
    const u64 hd0 = pk2(h0, h0);
    const u64 hd1 = pk2(h1, h1);
    const u64 hd2 = pk2(h2, h2);
    const u64 hd3 = pk2(h3, h3);
    const u64 hd4 = pk2(h4, h4);
    const u64 hd5 = pk2(h5, h5);
    const u64 hd6 = pk2(h6, h6);
    const u64 hd7 = pk2(h7, h7);
    const u64 hn2p = pk2(hn2, hn2);

    // Lane-separated accumulators: lane0 = even codes, lane1 = odd codes
    u64 acc0 = 0ull, acc1 = 0ull, acc2 = 0ull, acc3 = 0ull;
    u64 acc4 = 0ull, acc5 = 0ull, acc6 = 0ull, acc7 = 0ull;
    u64 sume2 = 0ull;
    float mind = 3.4e38f;
    int   mink = 0;

    #pragma unroll 8
    for (int j = 0; j < KCODES / 2; j++) {
        const ulonglong2 q01 = reinterpret_cast<const ulonglong2*>(sct[j])[0];
        const ulonglong2 q23 = reinterpret_cast<const ulonglong2*>(sct[j])[1];
        const ulonglong2 q45 = reinterpret_cast<const ulonglong2*>(sct[j])[2];
        const ulonglong2 q67 = reinterpret_cast<const ulonglong2*>(sct[j])[3];

        // d2' (both lanes) = (scn' + hn') + sum_i h_i * (S2n c_i)
        u64 dp = fadd2(ssn[j], hn2p);
        dp = ffma2(hd0, q01.x, dp);
        dp = ffma2(hd1, q01.y, dp);
        dp = ffma2(hd2, q23.x, dp);
        dp = ffma2(hd3, q23.y, dp);
        dp = ffma2(hd4, q45.x, dp);
        dp = ffma2(hd5, q45.y, dp);
        dp = ffma2(hd6, q67.x, dp);
        dp = ffma2(hd7, q67.y, dp);

        float d2a, d2b;
        upk2(dp, d2a, d2b);

        // argmin (exact compare on scaled d2; positive scale preserves order,
        // strict '<' and ascending k preserve first-min semantics)
        if (d2a < mind) { mind = d2a; mink = 2 * j; }
        if (d2b < mind) { mind = d2b; mink = 2 * j + 1; }

        // e = exp(-dist) = 2^(-sqrt(S1*d2))
        const float e0 = ex2_ap(-sqrt_ap(fabsf(d2a)));
        const float e1 = ex2_ap(-sqrt_ap(fabsf(d2b)));
        const u64 ep = pk2(e0, e1);
        sume2 = fadd2(sume2, ep);

        acc0 = ffma2(ep, q01.x, acc0);
        acc1 = ffma2(ep, q01.y, acc1);
        acc2 = ffma2(ep, q23.x, acc2);
        acc3 = ffma2(ep, q23.y, acc3);
        acc4 = ffma2(ep, q45.x, acc4);
        acc5 = ffma2(ep, q45.y, acc5);
        acc6 = ffma2(ep, q67.x, acc6);
        acc7 = ffma2(ep, q67.y, acc7);
    }

    float se0, se1;
    upk2(sume2, se0, se1);
    const float inv = INV_S2n / (se0 + se1);

    float lo, hi, s0, s1, s2, s3, s4, s5, s6, s7;
    upk2(acc0, lo, hi); s0 = (lo + hi) * inv;
    upk2(acc1, lo, hi); s1 = (lo + hi) * inv;
    upk2(acc2, lo, hi); s2 = (lo + hi) * inv;
    upk2(acc3, lo, hi); s3 = (lo + hi) * inv;
    upk2(acc4, lo, hi); s4 = (lo + hi) * inv;
    upk2(acc5, lo, hi); s5 = (lo + hi) * inv;
    upk2(acc6, lo, hi); s6 = (lo + hi) * inv;
    upk2(acc7, lo, hi); s7 = (lo + hi) * inv;

    // soft: (B,W,H,C), c = l*8 + cd -> offset pos*128 + l*8 (32B-aligned)
    {
        float4* sp = reinterpret_cast<float4*>(out_soft + (size_t)pos * ZC + (size_t)l * CDIM);
        sp[0] = make_float4(s0, s1, s2, s3);
        sp[1] = make_float4(s4, s5, s6, s7);
    }
    if (out_hard) {
        // Winning code re-read from global (L2-hot, 32B)
        const float4* cw = reinterpret_cast<const float4*>(codes)
                         + ((size_t)l * KCODES + mink) * 2;
        float4* hp = reinterpret_cast<float4*>(out_hard + (size_t)pos * ZC + (size_t)l * CDIM);
        hp[0] = cw[0];
        hp[1] = cw[1];
    }
    if (out_idx) {
        out_idx[(size_t)pos * LDIM + l] = (float)mink;
    }
}

extern "C" void kernel_launch(void* const* d_in, const int* in_sizes, int n_in,
                              void* d_out, int out_size) {
    const float* z     = (const float*)d_in[0];
    const float* codes = (const float*)d_in[1];
    float* out = (float*)d_out;

    const long long softN = (long long)NPOS * ZC;   // 4,194,304
    const long long idxN  = (long long)NPOS * LDIM; // 524,288

    float* soft = out;
    float* hard = ((long long)out_size >= 2 * softN) ? out + softN : nullptr;
    float* idxo = ((long long)out_size >= 2 * softN + idxN) ? out + 2 * softN : nullptr;

    dim3 grid(NPOS / 256, LDIM);
    sth_kernel<<<grid, 256>>>(z, codes, soft, hard, idxo);
}